// round 2
// baseline (speedup 1.0000x reference)
#include <cuda_runtime.h>

// Problem constants
#define N_ 100000
#define E_ 3200000

// ---------------------------------------------------------------------------
// Scratch (no allocations allowed -> __device__ globals)
// ---------------------------------------------------------------------------
__device__ float g_buf0[100000 * 256];
__device__ float g_buf1[100000 * 256];
__device__ float g_buf2[100000 * 256];
__device__ int   g_deg[N_];
__device__ int   g_rowptr[N_ + 1];
__device__ int   g_pos[N_];
__device__ int   g_col[E_];
__device__ float g_bn_s[3 * 256];
__device__ float g_bn_b[3 * 256];

// ---------------------------------------------------------------------------
// CSR build: histogram -> scan -> fill
// ---------------------------------------------------------------------------
__global__ void k_zero_deg() {
    int i = blockIdx.x * blockDim.x + threadIdx.x;
    if (i < N_) g_deg[i] = 0;
}

__global__ void k_count(const int* __restrict__ dst) {
    for (int e = blockIdx.x * blockDim.x + threadIdx.x; e < E_;
         e += gridDim.x * blockDim.x)
        atomicAdd(&g_deg[dst[e]], 1);
}

// Single-block scan over N_ (chunks of 1024). N_=100k -> 98 chunks, cheap.
__global__ void k_scan() {
    __shared__ int wsum[32];
    int tid = threadIdx.x, lane = tid & 31, wid = tid >> 5;
    int carry = 0;
    for (int base = 0; base < N_; base += 1024) {
        int i = base + tid;
        int v = (i < N_) ? g_deg[i] : 0;
        int x = v;
#pragma unroll
        for (int d = 1; d < 32; d <<= 1) {
            int y = __shfl_up_sync(0xffffffffu, x, d);
            if (lane >= d) x += y;
        }
        if (lane == 31) wsum[wid] = x;
        __syncthreads();
        if (wid == 0) {
            int w = wsum[lane];
#pragma unroll
            for (int d = 1; d < 32; d <<= 1) {
                int y = __shfl_up_sync(0xffffffffu, w, d);
                if (lane >= d) w += y;
            }
            wsum[lane] = w;
        }
        __syncthreads();
        int off = carry + (wid ? wsum[wid - 1] : 0);
        if (i < N_) g_rowptr[i + 1] = off + x;
        int tot = wsum[31];
        __syncthreads();
        carry += tot;
    }
    if (tid == 0) g_rowptr[0] = 0;
}

__global__ void k_pos() {
    int i = blockIdx.x * blockDim.x + threadIdx.x;
    if (i < N_) g_pos[i] = g_rowptr[i];
}

__global__ void k_fill(const int* __restrict__ src, const int* __restrict__ dst) {
    for (int e = blockIdx.x * blockDim.x + threadIdx.x; e < E_;
         e += gridDim.x * blockDim.x) {
        int idx = atomicAdd(&g_pos[dst[e]], 1);
        g_col[idx] = src[e];
    }
}

// ---------------------------------------------------------------------------
// Fold BatchNorm(inference) + Linear bias into per-column scale/bias:
//   y = (zW1+b1 - mu)*rsqrt(var+eps)*g + be  =  (zW1)*s + ((b1-mu)*s + be)
// ---------------------------------------------------------------------------
__global__ void k_bnprep(const float* __restrict__ b1, const float* __restrict__ g,
                         const float* __restrict__ be, const float* __restrict__ mu,
                         const float* __restrict__ var, int off) {
    int c = threadIdx.x;
    float s = g[c] * rsqrtf(var[c] + 1e-5f);
    g_bn_s[off + c] = s;
    g_bn_b[off + c] = (b1[c] - mu[c]) * s + be[c];
}

// ---------------------------------------------------------------------------
// Aggregation: z[i] = h[i] + sum_{j in CSR(i)} h[j]  — warp per node, gather.
// ---------------------------------------------------------------------------
__device__ __forceinline__ float4 f4add(float4 a, float4 b) {
    a.x += b.x; a.y += b.y; a.z += b.z; a.w += b.w; return a;
}

template <int HD>
__global__ void k_agg(const float* __restrict__ hin, float* __restrict__ zout) {
    int warp = (blockIdx.x * blockDim.x + threadIdx.x) >> 5;
    int lane = threadIdx.x & 31;
    if (warp >= N_) return;
    const int C4 = HD / 4;  // 32 or 64
    const float4* h4 = (const float4*)hin;
    const float4* self = h4 + (size_t)warp * C4;
    float4 a0 = self[lane];
    float4 a1 = make_float4(0.f, 0.f, 0.f, 0.f);
    if (HD == 256) a1 = self[lane + 32];

    int e = g_rowptr[warp];
    int end = g_rowptr[warp + 1];
    for (; e + 2 <= end; e += 2) {
        int j0 = g_col[e], j1 = g_col[e + 1];
        const float4* r0 = h4 + (size_t)j0 * C4;
        const float4* r1 = h4 + (size_t)j1 * C4;
        float4 v0 = r0[lane];
        float4 v1 = r1[lane];
        if (HD == 256) {
            float4 w0 = r0[lane + 32];
            float4 w1 = r1[lane + 32];
            a1 = f4add(a1, f4add(w0, w1));
        }
        a0 = f4add(a0, f4add(v0, v1));
    }
    if (e < end) {
        const float4* r0 = h4 + (size_t)g_col[e] * C4;
        a0 = f4add(a0, r0[lane]);
        if (HD == 256) a1 = f4add(a1, r0[lane + 32]);
    }
    float4* z4 = (float4*)zout + (size_t)warp * C4;
    z4[lane] = a0;
    if (HD == 256) z4[lane + 32] = a1;
}

// ---------------------------------------------------------------------------
// SGEMM: C[rows,256] = A[rows,K] @ B[K,256] with fused epilogue.
//   EPI==0: val = val*g_bn_s[bn_off+c] + g_bn_b[bn_off+c]   (BN fold)
//   EPI==1: val = val + bias[c]
//   RELU: optional
// Block tile 128x128, 256 threads, 8x8 per thread, BK=16.
// ---------------------------------------------------------------------------
template <int EPI, bool RELU>
__global__ __launch_bounds__(256) void k_sgemm(
    const float* __restrict__ A, const float* __restrict__ B,
    const float* __restrict__ bias, int bn_off,
    float* __restrict__ C, int rows, int K) {
    __shared__ float As[16][132];
    __shared__ float Bs[16][132];

    int tid = threadIdx.x;
    int tx = tid & 15, ty = tid >> 4;
    int rowbase = blockIdx.y * 128;
    int colbase = blockIdx.x * 128;  // M = 256 fixed

    float acc[8][8];
#pragma unroll
    for (int i = 0; i < 8; i++)
#pragma unroll
        for (int j = 0; j < 8; j++) acc[i][j] = 0.f;

    int arow0 = tid >> 2, ac4 = tid & 3;
    int arow1 = arow0 + 64;
    int brow0 = tid >> 5, bc4 = tid & 31;
    int brow1 = brow0 + 8;

    for (int k0 = 0; k0 < K; k0 += 16) {
        // A tile (transposed into smem)
        {
            int r = rowbase + arow0;
            float4 v = make_float4(0.f, 0.f, 0.f, 0.f);
            if (r < rows) v = *(const float4*)(A + (size_t)r * K + k0 + ac4 * 4);
            As[ac4 * 4 + 0][arow0] = v.x;
            As[ac4 * 4 + 1][arow0] = v.y;
            As[ac4 * 4 + 2][arow0] = v.z;
            As[ac4 * 4 + 3][arow0] = v.w;
            r = rowbase + arow1;
            v = make_float4(0.f, 0.f, 0.f, 0.f);
            if (r < rows) v = *(const float4*)(A + (size_t)r * K + k0 + ac4 * 4);
            As[ac4 * 4 + 0][arow1] = v.x;
            As[ac4 * 4 + 1][arow1] = v.y;
            As[ac4 * 4 + 2][arow1] = v.z;
            As[ac4 * 4 + 3][arow1] = v.w;
        }
        // B tile (direct)
        {
            float4 v = *(const float4*)(B + (size_t)(k0 + brow0) * 256 + colbase + bc4 * 4);
            *(float4*)&Bs[brow0][bc4 * 4] = v;
            v = *(const float4*)(B + (size_t)(k0 + brow1) * 256 + colbase + bc4 * 4);
            *(float4*)&Bs[brow1][bc4 * 4] = v;
        }
        __syncthreads();
#pragma unroll
        for (int k = 0; k < 16; k++) {
            float a[8], bb[8];
            *(float4*)&a[0] = *(const float4*)&As[k][ty * 8];
            *(float4*)&a[4] = *(const float4*)&As[k][ty * 8 + 4];
            *(float4*)&bb[0] = *(const float4*)&Bs[k][tx * 8];
            *(float4*)&bb[4] = *(const float4*)&Bs[k][tx * 8 + 4];
#pragma unroll
            for (int i = 0; i < 8; i++)
#pragma unroll
                for (int j = 0; j < 8; j++) acc[i][j] += a[i] * bb[j];
        }
        __syncthreads();
    }

    // Epilogue
    float sc[8], bi[8];
#pragma unroll
    for (int j = 0; j < 8; j++) {
        int c = colbase + tx * 8 + j;
        if (EPI == 0) {
            sc[j] = g_bn_s[bn_off + c];
            bi[j] = g_bn_b[bn_off + c];
        } else {
            sc[j] = 1.f;
            bi[j] = bias[c];
        }
    }
#pragma unroll
    for (int i = 0; i < 8; i++) {
        int r = rowbase + ty * 8 + i;
        if (r >= rows) continue;
        float o[8];
#pragma unroll
        for (int j = 0; j < 8; j++) {
            float v = acc[i][j];
            if (EPI == 0) v = v * sc[j] + bi[j];
            else v = v + bi[j];
            if (RELU) v = fmaxf(v, 0.f);
            o[j] = v;
        }
        float* cp = C + (size_t)r * 256 + colbase + tx * 8;
        *(float4*)(cp) = make_float4(o[0], o[1], o[2], o[3]);
        *(float4*)(cp + 4) = make_float4(o[4], o[5], o[6], o[7]);
    }
}

// ---------------------------------------------------------------------------
// Output head: out[N,2] = h[N,256] @ W[256,2] + b. Warp per node.
// ---------------------------------------------------------------------------
__global__ void k_out(const float* __restrict__ h, const float* __restrict__ W,
                      const float* __restrict__ bo, float* __restrict__ out) {
    int warp = (blockIdx.x * blockDim.x + threadIdx.x) >> 5;
    int lane = threadIdx.x & 31;
    if (warp >= N_) return;
    const float* row = h + (size_t)warp * 256;
    float a0 = 0.f, a1 = 0.f;
#pragma unroll
    for (int k = lane; k < 256; k += 32) {
        float v = row[k];
        a0 += v * W[k * 2 + 0];
        a1 += v * W[k * 2 + 1];
    }
#pragma unroll
    for (int d = 16; d > 0; d >>= 1) {
        a0 += __shfl_down_sync(0xffffffffu, a0, d);
        a1 += __shfl_down_sync(0xffffffffu, a1, d);
    }
    if (lane == 0) {
        out[(size_t)warp * 2 + 0] = a0 + bo[0];
        out[(size_t)warp * 2 + 1] = a1 + bo[1];
    }
}

// ---------------------------------------------------------------------------
// Launch
// ---------------------------------------------------------------------------
extern "C" void kernel_launch(void* const* d_in, const int* in_sizes, int n_in,
                              void* d_out, int out_size) {
    const float* x = (const float*)d_in[0];
    const int* ei = (const int*)d_in[1];
    const int* src = ei;
    const int* dst = ei + E_;
    // Layers: W1,b1,g,be,mu,var,W2,b2
    const float* L[3][8];
    for (int l = 0; l < 3; l++)
        for (int p = 0; p < 8; p++)
            L[l][p] = (const float*)d_in[2 + l * 8 + p];
    const float* outW = (const float*)d_in[26];
    const float* outb = (const float*)d_in[27];
    float* out = (float*)d_out;

    // CSR build (shared by all 3 layers)
    k_zero_deg<<<(N_ + 255) / 256, 256>>>();
    k_count<<<512, 256>>>(dst);
    k_scan<<<1, 1024>>>();
    k_pos<<<(N_ + 255) / 256, 256>>>();
    k_fill<<<512, 256>>>(src, dst);

    // BN folds
    for (int l = 0; l < 3; l++)
        k_bnprep<<<1, 256>>>(L[l][1], L[l][2], L[l][3], L[l][4], L[l][5], l * 256);

    dim3 gg(2, (N_ + 127) / 128);
    int aggBlocks = (N_ + 7) / 8;  // 8 warps per block

    // Layer 1 (F=128)
    k_agg<128><<<aggBlocks, 256>>>(x, g_buf0);
    k_sgemm<0, true><<<gg, 256>>>(g_buf0, L[0][0], nullptr, 0, g_buf1, N_, 128);
    k_sgemm<1, true><<<gg, 256>>>(g_buf1, L[0][6], L[0][7], 0, g_buf0, N_, 256);

    // Layer 2
    k_agg<256><<<aggBlocks, 256>>>(g_buf0, g_buf1);
    k_sgemm<0, true><<<gg, 256>>>(g_buf1, L[1][0], nullptr, 256, g_buf2, N_, 256);
    k_sgemm<1, true><<<gg, 256>>>(g_buf2, L[1][6], L[1][7], 0, g_buf0, N_, 256);

    // Layer 3 (no final ReLU)
    k_agg<256><<<aggBlocks, 256>>>(g_buf0, g_buf1);
    k_sgemm<0, true><<<gg, 256>>>(g_buf1, L[2][0], nullptr, 512, g_buf2, N_, 256);
    k_sgemm<1, false><<<gg, 256>>>(g_buf2, L[2][6], L[2][7], 0, g_buf0, N_, 256);

    // Output head
    k_out<<<(N_ + 7) / 8, 256>>>(g_buf0, outW, outb, out);
}

// round 3
// speedup vs baseline: 1.1819x; 1.1819x over previous
#include <cuda_runtime.h>

#define N_ 100000
#define E_ 3200000

// ---------------------------------------------------------------------------
// Scratch (no allocations allowed -> __device__ globals)
// ---------------------------------------------------------------------------
__device__ float g_buf0[100000 * 256];
__device__ float g_buf1[100000 * 256];
__device__ float g_buf2[100000 * 256];
__device__ int   g_deg[N_];
__device__ int   g_rowptr[N_ + 1];
__device__ int   g_pos[N_];
__device__ int   g_col[E_];

// ---------------------------------------------------------------------------
// CSR build: histogram -> scan(+pos) -> fill
// ---------------------------------------------------------------------------
__global__ void k_zero_deg() {
    int i = blockIdx.x * blockDim.x + threadIdx.x;
    if (i < N_) g_deg[i] = 0;
}

__global__ void k_count(const int* __restrict__ dst) {
    for (int e = blockIdx.x * blockDim.x + threadIdx.x; e < E_;
         e += gridDim.x * blockDim.x)
        atomicAdd(&g_deg[dst[e]], 1);
}

// Single-block scan over N_ (chunks of 1024). Also writes g_pos = exclusive sum.
__global__ void k_scan() {
    __shared__ int wsum[32];
    int tid = threadIdx.x, lane = tid & 31, wid = tid >> 5;
    int carry = 0;
    for (int base = 0; base < N_; base += 1024) {
        int i = base + tid;
        int v = (i < N_) ? g_deg[i] : 0;
        int x = v;
#pragma unroll
        for (int d = 1; d < 32; d <<= 1) {
            int y = __shfl_up_sync(0xffffffffu, x, d);
            if (lane >= d) x += y;
        }
        if (lane == 31) wsum[wid] = x;
        __syncthreads();
        if (wid == 0) {
            int w = wsum[lane];
#pragma unroll
            for (int d = 1; d < 32; d <<= 1) {
                int y = __shfl_up_sync(0xffffffffu, w, d);
                if (lane >= d) w += y;
            }
            wsum[lane] = w;
        }
        __syncthreads();
        int off = carry + (wid ? wsum[wid - 1] : 0);
        if (i < N_) {
            g_rowptr[i + 1] = off + x;
            g_pos[i] = off + x - v;  // exclusive prefix = rowptr[i]
        }
        int tot = wsum[31];
        __syncthreads();
        carry += tot;
    }
    if (tid == 0) g_rowptr[0] = 0;
}

__global__ void k_fill(const int* __restrict__ src, const int* __restrict__ dst) {
    for (int e = blockIdx.x * blockDim.x + threadIdx.x; e < E_;
         e += gridDim.x * blockDim.x) {
        int idx = atomicAdd(&g_pos[dst[e]], 1);
        g_col[idx] = src[e];
    }
}

// ---------------------------------------------------------------------------
// Aggregation: z[i] = h[i] + sum_{j in CSR(i)} h[j] — warp per node, gather.
// ---------------------------------------------------------------------------
__device__ __forceinline__ float4 f4add(float4 a, float4 b) {
    a.x += b.x; a.y += b.y; a.z += b.z; a.w += b.w; return a;
}

template <int HD>
__global__ void k_agg(const float* __restrict__ hin, float* __restrict__ zout) {
    int warp = (blockIdx.x * blockDim.x + threadIdx.x) >> 5;
    int lane = threadIdx.x & 31;
    if (warp >= N_) return;
    const int C4 = HD / 4;  // 32 or 64
    const float4* h4 = (const float4*)hin;
    const float4* self = h4 + (size_t)warp * C4;
    float4 a0 = self[lane];
    float4 a1 = make_float4(0.f, 0.f, 0.f, 0.f);
    if (HD == 256) a1 = self[lane + 32];

    int e = g_rowptr[warp];
    int end = g_rowptr[warp + 1];
    // 4-edge unroll for MLP
    for (; e + 4 <= end; e += 4) {
        int j0 = g_col[e], j1 = g_col[e + 1], j2 = g_col[e + 2], j3 = g_col[e + 3];
        const float4* r0 = h4 + (size_t)j0 * C4;
        const float4* r1 = h4 + (size_t)j1 * C4;
        const float4* r2 = h4 + (size_t)j2 * C4;
        const float4* r3 = h4 + (size_t)j3 * C4;
        float4 v0 = r0[lane], v1 = r1[lane], v2 = r2[lane], v3 = r3[lane];
        a0 = f4add(a0, f4add(f4add(v0, v1), f4add(v2, v3)));
        if (HD == 256) {
            float4 w0 = r0[lane + 32], w1 = r1[lane + 32];
            float4 w2 = r2[lane + 32], w3 = r3[lane + 32];
            a1 = f4add(a1, f4add(f4add(w0, w1), f4add(w2, w3)));
        }
    }
    for (; e < end; e++) {
        const float4* r0 = h4 + (size_t)g_col[e] * C4;
        a0 = f4add(a0, r0[lane]);
        if (HD == 256) a1 = f4add(a1, r0[lane + 32]);
    }
    float4* z4 = (float4*)zout + (size_t)warp * C4;
    z4[lane] = a0;
    if (HD == 256) z4[lane + 32] = a1;
}

// ---------------------------------------------------------------------------
// f32x2 packed-FMA helpers (ptxas never emits FFMA2 from C++; PTX-only)
// ---------------------------------------------------------------------------
__device__ __forceinline__ unsigned long long pk2(float lo, float hi) {
    unsigned long long r;
    asm("mov.b64 %0, {%1, %2};" : "=l"(r) : "f"(lo), "f"(hi));
    return r;
}
__device__ __forceinline__ void fma2(unsigned long long& d,
                                     unsigned long long a, unsigned long long b) {
    asm("fma.rn.f32x2 %0, %1, %2, %0;" : "+l"(d) : "l"(a), "l"(b));
}
__device__ __forceinline__ float2 upk2(unsigned long long v) {
    float2 f;
    asm("mov.b64 {%0, %1}, %2;" : "=f"(f.x), "=f"(f.y) : "l"(v));
    return f;
}

// ---------------------------------------------------------------------------
// SGEMM: C[rows,256] = A[rows,K] @ B[K,256], fused epilogue.
//  EPI==0: BN fold computed in-kernel from (b1,g,be,mu,var):
//          s = g*rsqrt(var+eps); out = v*s + (b1-mu)*s + be
//  EPI==1: out = v + bias (e0)
// Block tile 128x128, 256 threads, 8x8/thread via f32x2 pairs, BK=16.
// Fragment mapping: cols = tx*4 + {0..3} and tx*4+64 + {0..3}  (conflict-free LDS)
//                   rows = ty*4 + {0..3} and ty*4+64 + {0..3}
// ---------------------------------------------------------------------------
template <int EPI, bool RELU>
__global__ __launch_bounds__(256, 2) void k_sgemm(
    const float* __restrict__ A, const float* __restrict__ B,
    const float* __restrict__ e0, const float* __restrict__ e1,
    const float* __restrict__ e2, const float* __restrict__ e3,
    const float* __restrict__ e4,
    float* __restrict__ C, int rows, int K) {
    __shared__ float As[16][132];
    __shared__ float Bs[16][132];

    int tid = threadIdx.x;
    int tx = tid & 15, ty = tid >> 4;
    int rowbase = blockIdx.y * 128;
    int colbase = blockIdx.x * 128;

    unsigned long long acc[8][4];
#pragma unroll
    for (int i = 0; i < 8; i++)
#pragma unroll
        for (int j = 0; j < 4; j++) acc[i][j] = 0ull;

    int arow0 = tid >> 2, ac4 = tid & 3;
    int arow1 = arow0 + 64;
    int brow0 = tid >> 5, bc4 = tid & 31;
    int brow1 = brow0 + 8;

    for (int k0 = 0; k0 < K; k0 += 16) {
        // A tile, transposed into smem
        {
            int r = rowbase + arow0;
            float4 v = make_float4(0.f, 0.f, 0.f, 0.f);
            if (r < rows) v = *(const float4*)(A + (size_t)r * K + k0 + ac4 * 4);
            As[ac4 * 4 + 0][arow0] = v.x;
            As[ac4 * 4 + 1][arow0] = v.y;
            As[ac4 * 4 + 2][arow0] = v.z;
            As[ac4 * 4 + 3][arow0] = v.w;
            r = rowbase + arow1;
            v = make_float4(0.f, 0.f, 0.f, 0.f);
            if (r < rows) v = *(const float4*)(A + (size_t)r * K + k0 + ac4 * 4);
            As[ac4 * 4 + 0][arow1] = v.x;
            As[ac4 * 4 + 1][arow1] = v.y;
            As[ac4 * 4 + 2][arow1] = v.z;
            As[ac4 * 4 + 3][arow1] = v.w;
        }
        // B tile, direct
        {
            float4 v = *(const float4*)(B + (size_t)(k0 + brow0) * 256 + colbase + bc4 * 4);
            *(float4*)&Bs[brow0][bc4 * 4] = v;
            v = *(const float4*)(B + (size_t)(k0 + brow1) * 256 + colbase + bc4 * 4);
            *(float4*)&Bs[brow1][bc4 * 4] = v;
        }
        __syncthreads();
#pragma unroll
        for (int k = 0; k < 16; k++) {
            float4 a0 = *(const float4*)&As[k][ty * 4];
            float4 a1 = *(const float4*)&As[k][ty * 4 + 64];
            float4 b0 = *(const float4*)&Bs[k][tx * 4];
            float4 b1 = *(const float4*)&Bs[k][tx * 4 + 64];
            unsigned long long bp0 = pk2(b0.x, b0.y);
            unsigned long long bp1 = pk2(b0.z, b0.w);
            unsigned long long bp2 = pk2(b1.x, b1.y);
            unsigned long long bp3 = pk2(b1.z, b1.w);
            float ar0 = a0.x, ar1 = a0.y, ar2 = a0.z, ar3 = a0.w;
            float ar4 = a1.x, ar5 = a1.y, ar6 = a1.z, ar7 = a1.w;
#define ROWFMA(i, av)                                  \
            {                                          \
                unsigned long long ap = pk2(av, av);   \
                fma2(acc[i][0], ap, bp0);              \
                fma2(acc[i][1], ap, bp1);              \
                fma2(acc[i][2], ap, bp2);              \
                fma2(acc[i][3], ap, bp3);              \
            }
            ROWFMA(0, ar0) ROWFMA(1, ar1) ROWFMA(2, ar2) ROWFMA(3, ar3)
            ROWFMA(4, ar4) ROWFMA(5, ar5) ROWFMA(6, ar6) ROWFMA(7, ar7)
#undef ROWFMA
        }
        __syncthreads();
    }

    // Epilogue: per-column scale/bias for this thread's 8 columns
    float sc[8], bi[8];
#pragma unroll
    for (int j = 0; j < 8; j++) {
        int c = colbase + tx * 4 + ((j < 4) ? j : (60 + j));
        if (EPI == 0) {
            float s = e1[c] * rsqrtf(e4[c] + 1e-5f);      // g * rsqrt(var+eps)
            sc[j] = s;
            bi[j] = (e0[c] - e3[c]) * s + e2[c];          // (b1-mu)*s + be
        } else {
            sc[j] = 1.f;
            bi[j] = e0[c];                                // bias
        }
    }
#pragma unroll
    for (int i = 0; i < 8; i++) {
        int r = rowbase + ty * 4 + ((i < 4) ? i : (60 + i));
        if (r >= rows) continue;
        float2 p0 = upk2(acc[i][0]);
        float2 p1 = upk2(acc[i][1]);
        float2 p2 = upk2(acc[i][2]);
        float2 p3 = upk2(acc[i][3]);
        float o[8] = {p0.x, p0.y, p1.x, p1.y, p2.x, p2.y, p3.x, p3.y};
#pragma unroll
        for (int j = 0; j < 8; j++) {
            float v = o[j] * sc[j] + bi[j];
            if (RELU) v = fmaxf(v, 0.f);
            o[j] = v;
        }
        float* cp = C + (size_t)r * 256 + colbase + tx * 4;
        *(float4*)(cp)      = make_float4(o[0], o[1], o[2], o[3]);
        *(float4*)(cp + 64) = make_float4(o[4], o[5], o[6], o[7]);
    }
}

// ---------------------------------------------------------------------------
// Output head: out[N,2] = h[N,256] @ W[256,2] + b. Warp per node.
// ---------------------------------------------------------------------------
__global__ void k_out(const float* __restrict__ h, const float* __restrict__ W,
                      const float* __restrict__ bo, float* __restrict__ out) {
    int warp = (blockIdx.x * blockDim.x + threadIdx.x) >> 5;
    int lane = threadIdx.x & 31;
    if (warp >= N_) return;
    const float* row = h + (size_t)warp * 256;
    float a0 = 0.f, a1 = 0.f;
#pragma unroll
    for (int k = lane; k < 256; k += 32) {
        float v = row[k];
        a0 += v * W[k * 2 + 0];
        a1 += v * W[k * 2 + 1];
    }
#pragma unroll
    for (int d = 16; d > 0; d >>= 1) {
        a0 += __shfl_down_sync(0xffffffffu, a0, d);
        a1 += __shfl_down_sync(0xffffffffu, a1, d);
    }
    if (lane == 0) {
        out[(size_t)warp * 2 + 0] = a0 + bo[0];
        out[(size_t)warp * 2 + 1] = a1 + bo[1];
    }
}

// ---------------------------------------------------------------------------
// Launch. Order matters for ncu (-s 5 -c 1): launch #5 = first big SGEMM.
// ---------------------------------------------------------------------------
extern "C" void kernel_launch(void* const* d_in, const int* in_sizes, int n_in,
                              void* d_out, int out_size) {
    const float* x = (const float*)d_in[0];
    const int* ei = (const int*)d_in[1];
    const int* src = ei;
    const int* dst = ei + E_;
    // Layers: W1,b1,g,be,mu,var,W2,b2
    const float* L[3][8];
    for (int l = 0; l < 3; l++)
        for (int p = 0; p < 8; p++)
            L[l][p] = (const float*)d_in[2 + l * 8 + p];
    const float* outW = (const float*)d_in[26];
    const float* outb = (const float*)d_in[27];
    float* out = (float*)d_out;

    // CSR build (shared by all 3 layers): 4 launches
    k_zero_deg<<<(N_ + 255) / 256, 256>>>();
    k_count<<<512, 256>>>(dst);
    k_scan<<<1, 1024>>>();
    k_fill<<<512, 256>>>(src, dst);

    dim3 gg(2, (N_ + 127) / 128);
    int aggBlocks = (N_ + 7) / 8;  // 8 warps/block

    // Layer 1 (F=128) — agg is launch #4, sgemm is launch #5 (profiled)
    k_agg<128><<<aggBlocks, 256>>>(x, g_buf0);
    k_sgemm<0, true><<<gg, 256>>>(g_buf0, L[0][0], L[0][1], L[0][2], L[0][3],
                                  L[0][4], L[0][5], g_buf1, N_, 128);
    k_sgemm<1, true><<<gg, 256>>>(g_buf1, L[0][6], L[0][7], nullptr, nullptr,
                                  nullptr, nullptr, g_buf0, N_, 256);

    // Layer 2
    k_agg<256><<<aggBlocks, 256>>>(g_buf0, g_buf1);
    k_sgemm<0, true><<<gg, 256>>>(g_buf1, L[1][0], L[1][1], L[1][2], L[1][3],
                                  L[1][4], L[1][5], g_buf2, N_, 256);
    k_sgemm<1, true><<<gg, 256>>>(g_buf2, L[1][6], L[1][7], nullptr, nullptr,
                                  nullptr, nullptr, g_buf0, N_, 256);

    // Layer 3 (no final ReLU)
    k_agg<256><<<aggBlocks, 256>>>(g_buf0, g_buf1);
    k_sgemm<0, true><<<gg, 256>>>(g_buf1, L[2][0], L[2][1], L[2][2], L[2][3],
                                  L[2][4], L[2][5], g_buf2, N_, 256);
    k_sgemm<1, false><<<gg, 256>>>(g_buf2, L[2][6], L[2][7], nullptr, nullptr,
                                   nullptr, nullptr, g_buf0, N_, 256);

    // Output head
    k_out<<<(N_ + 7) / 8, 256>>>(g_buf0, outW, outb, out);
}

// round 12
// speedup vs baseline: 26.4077x; 22.3429x over previous
#include <cuda_runtime.h>
#include <cuda_bf16.h>
#include <cstdint>

#define N_ 100000
#define E_ 3200000

// ---------------------------------------------------------------------------
// Scratch (no allocations allowed -> __device__ globals; zero-initialized).
// IMPORTANT: host code must use cudaGetSymbolAddress to get device pointers.
// ---------------------------------------------------------------------------
__device__ float g_buf0[100000 * 256];
__device__ float g_buf1[100000 * 256];
__device__ int   g_deg[N_];           // invariant: zero at entry of each exec
__device__ int   g_rowptr[N_ + 1];
__device__ int   g_pos[N_];
__device__ int   g_col[E_];
// split-bf16 transposed weights [n=256][K] per matrix
__device__ __align__(16) __nv_bfloat16 g_wt_hi[360448];
__device__ __align__(16) __nv_bfloat16 g_wt_lo[360448];

// ---------------------------------------------------------------------------
// CSR build: count -> scan(+zero deg) -> fill   (all symbol refs device-side)
// ---------------------------------------------------------------------------
__global__ void k_count(const int* __restrict__ dst) {
    for (int e = blockIdx.x * blockDim.x + threadIdx.x; e < E_;
         e += gridDim.x * blockDim.x)
        atomicAdd(&g_deg[dst[e]], 1);
}

__global__ void k_scanzero() {
    __shared__ int wsum[32];
    int tid = threadIdx.x, lane = tid & 31, wid = tid >> 5;
    int carry = 0;
    for (int base = 0; base < N_; base += 1024) {
        int i = base + tid;
        int v = (i < N_) ? g_deg[i] : 0;
        int x = v;
#pragma unroll
        for (int d = 1; d < 32; d <<= 1) {
            int y = __shfl_up_sync(0xffffffffu, x, d);
            if (lane >= d) x += y;
        }
        if (lane == 31) wsum[wid] = x;
        __syncthreads();
        if (wid == 0) {
            int w = wsum[lane];
#pragma unroll
            for (int d = 1; d < 32; d <<= 1) {
                int y = __shfl_up_sync(0xffffffffu, w, d);
                if (lane >= d) w += y;
            }
            wsum[lane] = w;
        }
        __syncthreads();
        int off = carry + (wid ? wsum[wid - 1] : 0);
        if (i < N_) {
            g_rowptr[i + 1] = off + x;
            g_pos[i] = off + x - v;
            g_deg[i] = 0;  // restore invariant for next execution
        }
        int tot = wsum[31];
        __syncthreads();
        carry += tot;
    }
    if (tid == 0) g_rowptr[0] = 0;
}

__global__ void k_fill(const int* __restrict__ src, const int* __restrict__ dst) {
    for (int e = blockIdx.x * blockDim.x + threadIdx.x; e < E_;
         e += gridDim.x * blockDim.x) {
        int idx = atomicAdd(&g_pos[dst[e]], 1);
        g_col[idx] = src[e];
    }
}

// ---------------------------------------------------------------------------
// Aggregation: z[i] = h[i] + sum_j h[j] — warp per node, gather.
// ---------------------------------------------------------------------------
__device__ __forceinline__ float4 f4add(float4 a, float4 b) {
    a.x += b.x; a.y += b.y; a.z += b.z; a.w += b.w; return a;
}

template <int HD>
__global__ void k_agg(const float* __restrict__ hin, float* __restrict__ zout) {
    int warp = (blockIdx.x * blockDim.x + threadIdx.x) >> 5;
    int lane = threadIdx.x & 31;
    if (warp >= N_) return;
    const int C4 = HD / 4;
    const float4* h4 = (const float4*)hin;
    const float4* self = h4 + (size_t)warp * C4;
    float4 a0 = self[lane];
    float4 a1 = make_float4(0.f, 0.f, 0.f, 0.f);
    if (HD == 256) a1 = self[lane + 32];

    int e = g_rowptr[warp];
    int end = g_rowptr[warp + 1];
    for (; e + 4 <= end; e += 4) {
        int j0 = g_col[e], j1 = g_col[e + 1], j2 = g_col[e + 2], j3 = g_col[e + 3];
        const float4* r0 = h4 + (size_t)j0 * C4;
        const float4* r1 = h4 + (size_t)j1 * C4;
        const float4* r2 = h4 + (size_t)j2 * C4;
        const float4* r3 = h4 + (size_t)j3 * C4;
        float4 v0 = r0[lane], v1 = r1[lane], v2 = r2[lane], v3 = r3[lane];
        a0 = f4add(a0, f4add(f4add(v0, v1), f4add(v2, v3)));
        if (HD == 256) {
            float4 w0 = r0[lane + 32], w1 = r1[lane + 32];
            float4 w2 = r2[lane + 32], w3 = r3[lane + 32];
            a1 = f4add(a1, f4add(f4add(w0, w1), f4add(w2, w3)));
        }
    }
    for (; e < end; e++) {
        const float4* r0 = h4 + (size_t)g_col[e] * C4;
        a0 = f4add(a0, r0[lane]);
        if (HD == 256) a1 = f4add(a1, r0[lane + 32]);
    }
    float4* z4 = (float4*)zout + (size_t)warp * C4;
    z4[lane] = a0;
    if (HD == 256) z4[lane + 32] = a1;
}

// ---------------------------------------------------------------------------
// Weight prep: split fp32 W[K][256] -> transposed bf16 Wt_hi/lo[256][K].
// Writes through the SAME device pointers k_mma reads (wh/wl args).
// ---------------------------------------------------------------------------
__global__ void k_wprep(const float* w0, const float* w1, const float* w2,
                        const float* w3, const float* w4, const float* w5,
                        __nv_bfloat16* __restrict__ wh,
                        __nv_bfloat16* __restrict__ wl) {
    const int Ks[6] = {128, 256, 256, 256, 256, 256};
    const int offs[6] = {0, 32768, 98304, 163840, 229376, 294912};
    int z = blockIdx.z;
    const float* W = (z == 0) ? w0 : (z == 1) ? w1 : (z == 2) ? w2
                   : (z == 3) ? w3 : (z == 4) ? w4 : w5;
    int K = Ks[z], off = offs[z];
    int n = blockIdx.x;       // 0..255
    int k = threadIdx.x;      // 0..255
    if (k >= K) return;
    float v = W[(size_t)k * 256 + n];
    __nv_bfloat16 hi = __float2bfloat16(v);
    __nv_bfloat16 lo = __float2bfloat16(v - __bfloat162float(hi));
    wh[off + n * K + k] = hi;
    wl[off + n * K + k] = lo;
}

// ---------------------------------------------------------------------------
// mma.sync split-bf16 GEMM: C[rows,256] = A[rows,K] @ W[K,256] (+epilogue)
// Block 128x128, BK=32, 8 warps (2x4), warp tile 64x32.
// 3 products per k-step: Ah*Bh + Al*Bh + Ah*Bl into fp32 acc.
// Fragments via explicit LDS.32 per documented PTX layouts.
//  EPI==0: BN fold from (e0=b1,e1=g,e2=be,e3=mu,e4=var); EPI==1: +e0.
// ---------------------------------------------------------------------------
#define LDK 40  // padded smem row stride in bf16 (80B): conflict-free fragment LDS

__device__ __forceinline__ void mma16816(float* c, const uint32_t* a, const uint32_t* b) {
    asm volatile(
        "mma.sync.aligned.m16n8k16.row.col.f32.bf16.bf16.f32 "
        "{%0,%1,%2,%3}, {%4,%5,%6,%7}, {%8,%9}, {%0,%1,%2,%3};"
        : "+f"(c[0]), "+f"(c[1]), "+f"(c[2]), "+f"(c[3])
        : "r"(a[0]), "r"(a[1]), "r"(a[2]), "r"(a[3]), "r"(b[0]), "r"(b[1]));
}

template <int EPI, bool RELU>
__global__ __launch_bounds__(256) void k_mma(
    const float* __restrict__ A,
    const __nv_bfloat16* __restrict__ Bh, const __nv_bfloat16* __restrict__ Bl,
    const float* __restrict__ e0, const float* __restrict__ e1,
    const float* __restrict__ e2, const float* __restrict__ e3,
    const float* __restrict__ e4,
    float* __restrict__ C, int rows, int K) {
    __shared__ __align__(16) __nv_bfloat16 sAh[128 * LDK];
    __shared__ __align__(16) __nv_bfloat16 sAl[128 * LDK];
    __shared__ __align__(16) __nv_bfloat16 sBh[128 * LDK];
    __shared__ __align__(16) __nv_bfloat16 sBl[128 * LDK];

    int tid = threadIdx.x, wid = tid >> 5, lane = tid & 31;
    int warp_m = wid >> 2, warp_n = wid & 3;  // 2 x 4
    int rowbase = blockIdx.x * 128;
    int colbase = blockIdx.y * 128;
    int g = lane >> 2, tc = lane & 3;

    float acc[4][4][4];
#pragma unroll
    for (int i = 0; i < 4; i++)
#pragma unroll
        for (int j = 0; j < 4; j++)
#pragma unroll
            for (int q = 0; q < 4; q++) acc[i][j][q] = 0.f;

    int nchunk = K >> 5;
    for (int kc = 0; kc < nchunk; kc++) {
        int k0 = kc << 5;
        // ---- A: 128 rows x 32 fp32 -> split bf16 hi/lo ----
#pragma unroll
        for (int q = 0; q < 4; q++) {
            int f = q * 256 + tid;          // 1024 float4s: 8 per row
            int r = f >> 3, c4 = f & 7;
            int gr = rowbase + r;
            float4 v = make_float4(0.f, 0.f, 0.f, 0.f);
            if (gr < rows) v = *(const float4*)(A + (size_t)gr * K + k0 + c4 * 4);
            float hx = __bfloat162float(__float2bfloat16(v.x));
            float hy = __bfloat162float(__float2bfloat16(v.y));
            float hz = __bfloat162float(__float2bfloat16(v.z));
            float hw = __bfloat162float(__float2bfloat16(v.w));
            __nv_bfloat162 h01 = __floats2bfloat162_rn(v.x, v.y);
            __nv_bfloat162 h23 = __floats2bfloat162_rn(v.z, v.w);
            __nv_bfloat162 l01 = __floats2bfloat162_rn(v.x - hx, v.y - hy);
            __nv_bfloat162 l23 = __floats2bfloat162_rn(v.z - hz, v.w - hw);
            uint2 ph = make_uint2(*(uint32_t*)&h01, *(uint32_t*)&h23);
            uint2 pl = make_uint2(*(uint32_t*)&l01, *(uint32_t*)&l23);
            *(uint2*)&sAh[r * LDK + c4 * 4] = ph;
            *(uint2*)&sAl[r * LDK + c4 * 4] = pl;
        }
        // ---- B: 128 n-rows x 32 k bf16 hi/lo (pre-transposed [n][K]) ----
#pragma unroll
        for (int q = 0; q < 2; q++) {
            int i = q * 256 + tid;          // 512 uint4 per buffer: 4 per row
            int nr = i >> 2, c8 = i & 3;
            const uint4* sh = (const uint4*)(Bh + (size_t)(colbase + nr) * K + k0 + c8 * 8);
            const uint4* sl = (const uint4*)(Bl + (size_t)(colbase + nr) * K + k0 + c8 * 8);
            *(uint4*)&sBh[nr * LDK + c8 * 8] = *sh;
            *(uint4*)&sBl[nr * LDK + c8 * 8] = *sl;
        }
        __syncthreads();

#pragma unroll
        for (int ks = 0; ks < 32; ks += 16) {
            uint32_t ah[4][4], bh[4][2];
#pragma unroll
            for (int mt = 0; mt < 4; mt++) {
                int r = warp_m * 64 + mt * 16 + g;
                int b = r * LDK + ks + tc * 2;
                ah[mt][0] = *(const uint32_t*)&sAh[b];
                ah[mt][1] = *(const uint32_t*)&sAh[b + 8 * LDK];
                ah[mt][2] = *(const uint32_t*)&sAh[b + 8];
                ah[mt][3] = *(const uint32_t*)&sAh[b + 8 * LDK + 8];
            }
#pragma unroll
            for (int nt = 0; nt < 4; nt++) {
                int n = warp_n * 32 + nt * 8 + g;
                int b = n * LDK + ks + tc * 2;
                bh[nt][0] = *(const uint32_t*)&sBh[b];
                bh[nt][1] = *(const uint32_t*)&sBh[b + 8];
            }
            // hi*hi
#pragma unroll
            for (int mt = 0; mt < 4; mt++)
#pragma unroll
                for (int nt = 0; nt < 4; nt++)
                    mma16816(acc[mt][nt], ah[mt], bh[nt]);
            // lo*hi
            {
                uint32_t al[4][4];
#pragma unroll
                for (int mt = 0; mt < 4; mt++) {
                    int r = warp_m * 64 + mt * 16 + g;
                    int b = r * LDK + ks + tc * 2;
                    al[mt][0] = *(const uint32_t*)&sAl[b];
                    al[mt][1] = *(const uint32_t*)&sAl[b + 8 * LDK];
                    al[mt][2] = *(const uint32_t*)&sAl[b + 8];
                    al[mt][3] = *(const uint32_t*)&sAl[b + 8 * LDK + 8];
                }
#pragma unroll
                for (int mt = 0; mt < 4; mt++)
#pragma unroll
                    for (int nt = 0; nt < 4; nt++)
                        mma16816(acc[mt][nt], al[mt], bh[nt]);
            }
            // hi*lo
            {
                uint32_t bl[4][2];
#pragma unroll
                for (int nt = 0; nt < 4; nt++) {
                    int n = warp_n * 32 + nt * 8 + g;
                    int b = n * LDK + ks + tc * 2;
                    bl[nt][0] = *(const uint32_t*)&sBl[b];
                    bl[nt][1] = *(const uint32_t*)&sBl[b + 8];
                }
#pragma unroll
                for (int mt = 0; mt < 4; mt++)
#pragma unroll
                    for (int nt = 0; nt < 4; nt++)
                        mma16816(acc[mt][nt], ah[mt], bl[nt]);
            }
        }
        __syncthreads();
    }

    // ---- epilogue scale/bias into smem (reuse sAh) ----
    float* sc = (float*)sAh;
    float* bi = sc + 128;
    if (tid < 128) {
        int c = colbase + tid;
        if (EPI == 0) {
            float s = e1[c] * rsqrtf(e4[c] + 1e-5f);
            sc[tid] = s;
            bi[tid] = (e0[c] - e3[c]) * s + e2[c];
        } else {
            sc[tid] = 1.f;
            bi[tid] = e0[c];
        }
    }
    __syncthreads();

#pragma unroll
    for (int mt = 0; mt < 4; mt++) {
#pragma unroll
        for (int nt = 0; nt < 4; nt++) {
            int lc = warp_n * 32 + nt * 8 + tc * 2;
            int col = colbase + lc;
            float s0 = sc[lc], s1 = sc[lc + 1];
            float b0 = bi[lc], b1 = bi[lc + 1];
            int r0 = rowbase + warp_m * 64 + mt * 16 + g;
            float v0 = acc[mt][nt][0] * s0 + b0;
            float v1 = acc[mt][nt][1] * s1 + b1;
            float v2 = acc[mt][nt][2] * s0 + b0;
            float v3 = acc[mt][nt][3] * s1 + b1;
            if (RELU) {
                v0 = fmaxf(v0, 0.f); v1 = fmaxf(v1, 0.f);
                v2 = fmaxf(v2, 0.f); v3 = fmaxf(v3, 0.f);
            }
            if (r0 < rows) *(float2*)(C + (size_t)r0 * 256 + col) = make_float2(v0, v1);
            if (r0 + 8 < rows) *(float2*)(C + (size_t)(r0 + 8) * 256 + col) = make_float2(v2, v3);
        }
    }
}

// ---------------------------------------------------------------------------
// Output head: out[N,2] = h[N,256] @ W[256,2] + b. Warp per node.
// ---------------------------------------------------------------------------
__global__ void k_out(const float* __restrict__ h, const float* __restrict__ W,
                      const float* __restrict__ bo, float* __restrict__ out) {
    int warp = (blockIdx.x * blockDim.x + threadIdx.x) >> 5;
    int lane = threadIdx.x & 31;
    if (warp >= N_) return;
    const float* row = h + (size_t)warp * 256;
    float a0 = 0.f, a1 = 0.f;
#pragma unroll
    for (int k = lane; k < 256; k += 32) {
        float v = row[k];
        a0 += v * W[k * 2 + 0];
        a1 += v * W[k * 2 + 1];
    }
#pragma unroll
    for (int d = 16; d > 0; d >>= 1) {
        a0 += __shfl_down_sync(0xffffffffu, a0, d);
        a1 += __shfl_down_sync(0xffffffffu, a1, d);
    }
    if (lane == 0) {
        out[(size_t)warp * 2 + 0] = a0 + bo[0];
        out[(size_t)warp * 2 + 1] = a1 + bo[1];
    }
}

// ---------------------------------------------------------------------------
// Launch. All scratch buffers resolved with cudaGetSymbolAddress (true device
// addresses). Host-shadow symbol addresses silently resolve to host memory
// via GB300 ATS -> zeros/200GB/s; never pass bare symbols from host.
// ---------------------------------------------------------------------------
extern "C" void kernel_launch(void* const* d_in, const int* in_sizes, int n_in,
                              void* d_out, int out_size) {
    const float* x = (const float*)d_in[0];
    const int* ei = (const int*)d_in[1];
    const int* src = ei;
    const int* dst = ei + E_;
    const float* L[3][8];
    for (int l = 0; l < 3; l++)
        for (int p = 0; p < 8; p++)
            L[l][p] = (const float*)d_in[2 + l * 8 + p];
    const float* outW = (const float*)d_in[26];
    const float* outb = (const float*)d_in[27];
    float* out = (float*)d_out;

    // True device pointers for all cross-kernel scratch
    float *b0p = nullptr, *b1p = nullptr;
    __nv_bfloat16 *whp = nullptr, *wlp = nullptr;
    cudaGetSymbolAddress((void**)&b0p, g_buf0);
    cudaGetSymbolAddress((void**)&b1p, g_buf1);
    cudaGetSymbolAddress((void**)&whp, g_wt_hi);
    cudaGetSymbolAddress((void**)&wlp, g_wt_lo);

    // CSR: count(0), scanzero(1), fill(2)
    k_count<<<512, 256>>>(dst);
    k_scanzero<<<1, 1024>>>();
    k_fill<<<512, 256>>>(src, dst);

    int aggBlocks = (N_ + 7) / 8;
    dim3 gg((N_ + 127) / 128, 2);  // 782 x 2

    // index 3 = k_agg<128> (ncu target)
    k_agg<128><<<aggBlocks, 256>>>(x, b0p);

    // weight split/transpose (once per launch)
    k_wprep<<<dim3(256, 1, 6), 256>>>(L[0][0], L[0][6], L[1][0], L[1][6],
                                      L[2][0], L[2][6], whp, wlp);

    // Layer 1 (K=128 for first GEMM)
    k_mma<0, true><<<gg, 256>>>(b0p, whp + 0, wlp + 0,
        L[0][1], L[0][2], L[0][3], L[0][4], L[0][5], b1p, N_, 128);
    k_mma<1, true><<<gg, 256>>>(b1p, whp + 32768, wlp + 32768,
        L[0][7], nullptr, nullptr, nullptr, nullptr, b0p, N_, 256);

    // Layer 2
    k_agg<256><<<aggBlocks, 256>>>(b0p, b1p);
    k_mma<0, true><<<gg, 256>>>(b1p, whp + 98304, wlp + 98304,
        L[1][1], L[1][2], L[1][3], L[1][4], L[1][5], b0p, N_, 256);
    k_mma<1, true><<<gg, 256>>>(b0p, whp + 163840, wlp + 163840,
        L[1][7], nullptr, nullptr, nullptr, nullptr, b1p, N_, 256);

    // Layer 3 (no final ReLU)
    k_agg<256><<<aggBlocks, 256>>>(b1p, b0p);
    k_mma<0, true><<<gg, 256>>>(b0p, whp + 229376, wlp + 229376,
        L[2][1], L[2][2], L[2][3], L[2][4], L[2][5], b1p, N_, 256);
    k_mma<1, false><<<gg, 256>>>(b1p, whp + 294912, wlp + 294912,
        L[2][7], nullptr, nullptr, nullptr, nullptr, b0p, N_, 256);

    // Output head
    k_out<<<(N_ + 7) / 8, 256>>>(b0p, outW, outb, out);
}

// round 15
// speedup vs baseline: 30.6973x; 1.1624x over previous
#include <cuda_runtime.h>
#include <cuda_bf16.h>
#include <cstdint>

#define N_ 100000
#define E_ 3200000

// ---------------------------------------------------------------------------
// Scratch (no allocations allowed -> __device__ globals; zero-initialized).
// Host code resolves these with cudaGetSymbolAddress (NEVER bare symbols:
// GB300 ATS silently dereferences the host shadow at 200GB/s/zeros).
// ---------------------------------------------------------------------------
__device__ float g_buf0[100000 * 256];
__device__ float g_buf1[100000 * 256];
__device__ int   g_deg[N_];           // invariant: zero at entry of each exec
__device__ int   g_rowptr[N_ + 1];
__device__ int   g_pos[N_];
__device__ int   g_col[E_];
__device__ __align__(16) __nv_bfloat16 g_wt_hi[360448];
__device__ __align__(16) __nv_bfloat16 g_wt_lo[360448];

// ---------------------------------------------------------------------------
// CSR build: count -> scan(+zero deg) -> fill
// ---------------------------------------------------------------------------
__global__ void k_count(const int* __restrict__ dst) {
    for (int e = blockIdx.x * blockDim.x + threadIdx.x; e < E_;
         e += gridDim.x * blockDim.x)
        atomicAdd(&g_deg[dst[e]], 1);
}

__global__ void k_scanzero() {
    __shared__ int wsum[32];
    int tid = threadIdx.x, lane = tid & 31, wid = tid >> 5;
    int carry = 0;
    for (int base = 0; base < N_; base += 1024) {
        int i = base + tid;
        int v = (i < N_) ? g_deg[i] : 0;
        int x = v;
#pragma unroll
        for (int d = 1; d < 32; d <<= 1) {
            int y = __shfl_up_sync(0xffffffffu, x, d);
            if (lane >= d) x += y;
        }
        if (lane == 31) wsum[wid] = x;
        __syncthreads();
        if (wid == 0) {
            int w = wsum[lane];
#pragma unroll
            for (int d = 1; d < 32; d <<= 1) {
                int y = __shfl_up_sync(0xffffffffu, w, d);
                if (lane >= d) w += y;
            }
            wsum[lane] = w;
        }
        __syncthreads();
        int off = carry + (wid ? wsum[wid - 1] : 0);
        if (i < N_) {
            g_rowptr[i + 1] = off + x;
            g_pos[i] = off + x - v;
            g_deg[i] = 0;
        }
        int tot = wsum[31];
        __syncthreads();
        carry += tot;
    }
    if (tid == 0) g_rowptr[0] = 0;
}

__global__ void k_fill(const int* __restrict__ src, const int* __restrict__ dst) {
    for (int e = blockIdx.x * blockDim.x + threadIdx.x; e < E_;
         e += gridDim.x * blockDim.x) {
        int idx = atomicAdd(&g_pos[dst[e]], 1);
        g_col[idx] = src[e];
    }
}

// ---------------------------------------------------------------------------
// Aggregation: z[i] = h[i] + sum_j h[j] — warp per node, gather.
// ---------------------------------------------------------------------------
__device__ __forceinline__ float4 f4add(float4 a, float4 b) {
    a.x += b.x; a.y += b.y; a.z += b.z; a.w += b.w; return a;
}

template <int HD>
__global__ void k_agg(const float* __restrict__ hin, float* __restrict__ zout) {
    int warp = (blockIdx.x * blockDim.x + threadIdx.x) >> 5;
    int lane = threadIdx.x & 31;
    if (warp >= N_) return;
    const int C4 = HD / 4;
    const float4* h4 = (const float4*)hin;
    const float4* self = h4 + (size_t)warp * C4;
    float4 a0 = self[lane];
    float4 a1 = make_float4(0.f, 0.f, 0.f, 0.f);
    if (HD == 256) a1 = self[lane + 32];

    int e = g_rowptr[warp];
    int end = g_rowptr[warp + 1];
    for (; e + 4 <= end; e += 4) {
        int j0 = g_col[e], j1 = g_col[e + 1], j2 = g_col[e + 2], j3 = g_col[e + 3];
        const float4* r0 = h4 + (size_t)j0 * C4;
        const float4* r1 = h4 + (size_t)j1 * C4;
        const float4* r2 = h4 + (size_t)j2 * C4;
        const float4* r3 = h4 + (size_t)j3 * C4;
        float4 v0 = r0[lane], v1 = r1[lane], v2 = r2[lane], v3 = r3[lane];
        a0 = f4add(a0, f4add(f4add(v0, v1), f4add(v2, v3)));
        if (HD == 256) {
            float4 w0 = r0[lane + 32], w1 = r1[lane + 32];
            float4 w2 = r2[lane + 32], w3 = r3[lane + 32];
            a1 = f4add(a1, f4add(f4add(w0, w1), f4add(w2, w3)));
        }
    }
    for (; e < end; e++) {
        const float4* r0 = h4 + (size_t)g_col[e] * C4;
        a0 = f4add(a0, r0[lane]);
        if (HD == 256) a1 = f4add(a1, r0[lane + 32]);
    }
    float4* z4 = (float4*)zout + (size_t)warp * C4;
    z4[lane] = a0;
    if (HD == 256) z4[lane + 32] = a1;
}

// ---------------------------------------------------------------------------
// Weight prep: split fp32 W[K][256] -> transposed bf16 Wt_hi/lo[256][K].
// ---------------------------------------------------------------------------
__global__ void k_wprep(const float* w0, const float* w1, const float* w2,
                        const float* w3, const float* w4, const float* w5,
                        __nv_bfloat16* __restrict__ wh,
                        __nv_bfloat16* __restrict__ wl) {
    const int Ks[6] = {128, 256, 256, 256, 256, 256};
    const int offs[6] = {0, 32768, 98304, 163840, 229376, 294912};
    int z = blockIdx.z;
    const float* W = (z == 0) ? w0 : (z == 1) ? w1 : (z == 2) ? w2
                   : (z == 3) ? w3 : (z == 4) ? w4 : w5;
    int K = Ks[z], off = offs[z];
    int n = blockIdx.x;
    int k = threadIdx.x;
    if (k >= K) return;
    float v = W[(size_t)k * 256 + n];
    __nv_bfloat16 hi = __float2bfloat16(v);
    __nv_bfloat16 lo = __float2bfloat16(v - __bfloat162float(hi));
    wh[off + n * K + k] = hi;
    wl[off + n * K + k] = lo;
}

// ---------------------------------------------------------------------------
// mma.sync split-bf16 GEMM, double-buffered + ldmatrix fragments.
// Block 128x128, BK=32, 8 warps (2x4), warp tile 64x32.
// Products: Ah*Bh + Al*Bh + Ah*Bl (fp32 acc).
//  EPI==0: BN fold from (e0=b1,e1=g,e2=be,e3=mu,e4=var); EPI==1: +e0.
// ---------------------------------------------------------------------------
#define LDK 40                         // smem row stride bf16: 80B, 16B-aligned,
                                       // (5r+c)%8 granules -> ldmatrix conflict-free
#define MAT_ELEMS (128 * LDK)          // 5120
#define STAGE_ELEMS (4 * MAT_ELEMS)    // 20480
#define SMEM_BYTES (2 * STAGE_ELEMS * 2)  // 81920

__device__ __forceinline__ uint32_t smem_u32(const void* p) {
    uint32_t a;
    asm("{ .reg .u64 t; cvta.to.shared.u64 t, %1; cvt.u32.u64 %0, t; }"
        : "=r"(a) : "l"(p));
    return a;
}
__device__ __forceinline__ void ldm4(uint32_t* r, uint32_t addr) {
    asm volatile("ldmatrix.sync.aligned.m8n8.x4.shared.b16 {%0,%1,%2,%3}, [%4];"
                 : "=r"(r[0]), "=r"(r[1]), "=r"(r[2]), "=r"(r[3]) : "r"(addr));
}
__device__ __forceinline__ void mma16816(float* c, const uint32_t* a, const uint32_t* b) {
    asm volatile(
        "mma.sync.aligned.m16n8k16.row.col.f32.bf16.bf16.f32 "
        "{%0,%1,%2,%3}, {%4,%5,%6,%7}, {%8,%9}, {%0,%1,%2,%3};"
        : "+f"(c[0]), "+f"(c[1]), "+f"(c[2]), "+f"(c[3])
        : "r"(a[0]), "r"(a[1]), "r"(a[2]), "r"(a[3]), "r"(b[0]), "r"(b[1]));
}

template <int EPI, bool RELU>
__global__ __launch_bounds__(256) void k_mma(
    const float* __restrict__ A,
    const __nv_bfloat16* __restrict__ Bh, const __nv_bfloat16* __restrict__ Bl,
    const float* __restrict__ e0, const float* __restrict__ e1,
    const float* __restrict__ e2, const float* __restrict__ e3,
    const float* __restrict__ e4,
    float* __restrict__ C, int rows, int K) {
    extern __shared__ __align__(16) __nv_bfloat16 sm[];

    int tid = threadIdx.x, wid = tid >> 5, lane = tid & 31;
    int warp_m = wid >> 2, warp_n = wid & 3;  // 2 x 4
    int rowbase = blockIdx.x * 128;
    int colbase = blockIdx.y * 128;

    float acc[4][4][4];
#pragma unroll
    for (int i = 0; i < 4; i++)
#pragma unroll
        for (int j = 0; j < 4; j++)
#pragma unroll
            for (int q = 0; q < 4; q++) acc[i][j][q] = 0.f;

    // per-thread load coordinates
    int ar = tid >> 3, ac4 = tid & 7;        // A: 8 float4/row over 4 q-steps
    int bnr = tid >> 2, bc8 = tid & 3;       // B: 4 uint4/row over 2 q-steps

    float4 av[4];
    uint4 bvh[2], bvl[2];

    int nchunk = K >> 5;

    // ---- prefetch chunk 0 ----
    {
        int k0 = 0;
#pragma unroll
        for (int q = 0; q < 4; q++) {
            int r = (q * 256 + tid) >> 3, c4 = (q * 256 + tid) & 7;
            int gr = rowbase + r;
            av[q] = (gr < rows) ? *(const float4*)(A + (size_t)gr * K + k0 + c4 * 4)
                                : make_float4(0.f, 0.f, 0.f, 0.f);
        }
#pragma unroll
        for (int q = 0; q < 2; q++) {
            int i = q * 256 + tid;
            int nr = i >> 2, c8 = i & 3;
            bvh[q] = *(const uint4*)(Bh + (size_t)(colbase + nr) * K + k0 + c8 * 8);
            bvl[q] = *(const uint4*)(Bl + (size_t)(colbase + nr) * K + k0 + c8 * 8);
        }
    }
    // ---- store chunk 0 to stage 0 ----
    {
        __nv_bfloat16* dAh = sm;
        __nv_bfloat16* dAl = sm + MAT_ELEMS;
        __nv_bfloat16* dBh = sm + 2 * MAT_ELEMS;
        __nv_bfloat16* dBl = sm + 3 * MAT_ELEMS;
#pragma unroll
        for (int q = 0; q < 4; q++) {
            int r = (q * 256 + tid) >> 3, c4 = (q * 256 + tid) & 7;
            float4 v = av[q];
            float hx = __bfloat162float(__float2bfloat16(v.x));
            float hy = __bfloat162float(__float2bfloat16(v.y));
            float hz = __bfloat162float(__float2bfloat16(v.z));
            float hw = __bfloat162float(__float2bfloat16(v.w));
            __nv_bfloat162 h01 = __floats2bfloat162_rn(v.x, v.y);
            __nv_bfloat162 h23 = __floats2bfloat162_rn(v.z, v.w);
            __nv_bfloat162 l01 = __floats2bfloat162_rn(v.x - hx, v.y - hy);
            __nv_bfloat162 l23 = __floats2bfloat162_rn(v.z - hz, v.w - hw);
            *(uint2*)&dAh[r * LDK + c4 * 4] = make_uint2(*(uint32_t*)&h01, *(uint32_t*)&h23);
            *(uint2*)&dAl[r * LDK + c4 * 4] = make_uint2(*(uint32_t*)&l01, *(uint32_t*)&l23);
        }
#pragma unroll
        for (int q = 0; q < 2; q++) {
            int i = q * 256 + tid;
            int nr = i >> 2, c8 = i & 3;
            *(uint4*)&dBh[nr * LDK + c8 * 8] = bvh[q];
            *(uint4*)&dBl[nr * LDK + c8 * 8] = bvl[q];
        }
    }
    __syncthreads();

    int mat = lane >> 3, r8 = lane & 7;
    int g = lane >> 2, tc = lane & 3;

    for (int kc = 0; kc < nchunk; kc++) {
        // ---- prefetch next chunk into registers (GMEM latency under MMA) ----
        if (kc + 1 < nchunk) {
            int k0 = (kc + 1) << 5;
#pragma unroll
            for (int q = 0; q < 4; q++) {
                int r = (q * 256 + tid) >> 3, c4 = (q * 256 + tid) & 7;
                int gr = rowbase + r;
                av[q] = (gr < rows) ? *(const float4*)(A + (size_t)gr * K + k0 + c4 * 4)
                                    : make_float4(0.f, 0.f, 0.f, 0.f);
            }
#pragma unroll
            for (int q = 0; q < 2; q++) {
                int i = q * 256 + tid;
                int nr = i >> 2, c8 = i & 3;
                bvh[q] = *(const uint4*)(Bh + (size_t)(colbase + nr) * K + k0 + c8 * 8);
                bvl[q] = *(const uint4*)(Bl + (size_t)(colbase + nr) * K + k0 + c8 * 8);
            }
        }

        // ---- MMA on current stage ----
        {
            int s = kc & 1;
            const __nv_bfloat16* pAh = sm + s * STAGE_ELEMS;
            const __nv_bfloat16* pAl = pAh + MAT_ELEMS;
            const __nv_bfloat16* pBh = pAh + 2 * MAT_ELEMS;
            const __nv_bfloat16* pBl = pAh + 3 * MAT_ELEMS;
            uint32_t uAh = smem_u32(pAh), uAl = smem_u32(pAl);
            uint32_t uBh = smem_u32(pBh), uBl = smem_u32(pBl);

#pragma unroll
            for (int ks = 0; ks < 32; ks += 16) {
                uint32_t ah[4][4], al[4][4], bh[4][2], bl[4][2];
#pragma unroll
                for (int mt = 0; mt < 4; mt++) {
                    int row = warp_m * 64 + mt * 16 + (mat & 1) * 8 + r8;
                    int col = ks + (mat >> 1) * 8;
                    uint32_t off = (uint32_t)(row * LDK + col) * 2;
                    ldm4(ah[mt], uAh + off);
                    ldm4(al[mt], uAl + off);
                }
#pragma unroll
                for (int np = 0; np < 2; np++) {
                    int n = warp_n * 32 + np * 16 + (mat >> 1) * 8 + r8;
                    int col = ks + (mat & 1) * 8;
                    uint32_t off = (uint32_t)(n * LDK + col) * 2;
                    uint32_t t[4];
                    ldm4(t, uBh + off);
                    bh[np * 2 + 0][0] = t[0]; bh[np * 2 + 0][1] = t[1];
                    bh[np * 2 + 1][0] = t[2]; bh[np * 2 + 1][1] = t[3];
                    ldm4(t, uBl + off);
                    bl[np * 2 + 0][0] = t[0]; bl[np * 2 + 0][1] = t[1];
                    bl[np * 2 + 1][0] = t[2]; bl[np * 2 + 1][1] = t[3];
                }
#pragma unroll
                for (int mt = 0; mt < 4; mt++)
#pragma unroll
                    for (int nt = 0; nt < 4; nt++) {
                        mma16816(acc[mt][nt], ah[mt], bh[nt]);
                        mma16816(acc[mt][nt], al[mt], bh[nt]);
                        mma16816(acc[mt][nt], ah[mt], bl[nt]);
                    }
            }
        }

        // ---- store prefetched chunk to other stage ----
        if (kc + 1 < nchunk) {
            int s = (kc + 1) & 1;
            __nv_bfloat16* dAh = sm + s * STAGE_ELEMS;
            __nv_bfloat16* dAl = dAh + MAT_ELEMS;
            __nv_bfloat16* dBh = dAh + 2 * MAT_ELEMS;
            __nv_bfloat16* dBl = dAh + 3 * MAT_ELEMS;
#pragma unroll
            for (int q = 0; q < 4; q++) {
                int r = (q * 256 + tid) >> 3, c4 = (q * 256 + tid) & 7;
                float4 v = av[q];
                float hx = __bfloat162float(__float2bfloat16(v.x));
                float hy = __bfloat162float(__float2bfloat16(v.y));
                float hz = __bfloat162float(__float2bfloat16(v.z));
                float hw = __bfloat162float(__float2bfloat16(v.w));
                __nv_bfloat162 h01 = __floats2bfloat162_rn(v.x, v.y);
                __nv_bfloat162 h23 = __floats2bfloat162_rn(v.z, v.w);
                __nv_bfloat162 l01 = __floats2bfloat162_rn(v.x - hx, v.y - hy);
                __nv_bfloat162 l23 = __floats2bfloat162_rn(v.z - hz, v.w - hw);
                *(uint2*)&dAh[r * LDK + c4 * 4] = make_uint2(*(uint32_t*)&h01, *(uint32_t*)&h23);
                *(uint2*)&dAl[r * LDK + c4 * 4] = make_uint2(*(uint32_t*)&l01, *(uint32_t*)&l23);
            }
#pragma unroll
            for (int q = 0; q < 2; q++) {
                int i = q * 256 + tid;
                int nr = i >> 2, c8 = i & 3;
                *(uint4*)&dBh[nr * LDK + c8 * 8] = bvh[q];
                *(uint4*)&dBl[nr * LDK + c8 * 8] = bvl[q];
            }
        }
        __syncthreads();
    }

    // ---- epilogue: per-column scale/bias via smem ----
    float* sc = (float*)sm;
    float* bi = sc + 128;
    if (tid < 128) {
        int c = colbase + tid;
        if (EPI == 0) {
            float s = e1[c] * rsqrtf(e4[c] + 1e-5f);
            sc[tid] = s;
            bi[tid] = (e0[c] - e3[c]) * s + e2[c];
        } else {
            sc[tid] = 1.f;
            bi[tid] = e0[c];
        }
    }
    __syncthreads();

#pragma unroll
    for (int mt = 0; mt < 4; mt++) {
#pragma unroll
        for (int nt = 0; nt < 4; nt++) {
            int lc = warp_n * 32 + nt * 8 + tc * 2;
            int col = colbase + lc;
            float s0 = sc[lc], s1 = sc[lc + 1];
            float b0 = bi[lc], b1 = bi[lc + 1];
            int r0 = rowbase + warp_m * 64 + mt * 16 + g;
            float v0 = acc[mt][nt][0] * s0 + b0;
            float v1 = acc[mt][nt][1] * s1 + b1;
            float v2 = acc[mt][nt][2] * s0 + b0;
            float v3 = acc[mt][nt][3] * s1 + b1;
            if (RELU) {
                v0 = fmaxf(v0, 0.f); v1 = fmaxf(v1, 0.f);
                v2 = fmaxf(v2, 0.f); v3 = fmaxf(v3, 0.f);
            }
            if (r0 < rows) *(float2*)(C + (size_t)r0 * 256 + col) = make_float2(v0, v1);
            if (r0 + 8 < rows) *(float2*)(C + (size_t)(r0 + 8) * 256 + col) = make_float2(v2, v3);
        }
    }
}

// ---------------------------------------------------------------------------
// Output head: out[N,2] = h[N,256] @ W[256,2] + b. Warp per node.
// ---------------------------------------------------------------------------
__global__ void k_out(const float* __restrict__ h, const float* __restrict__ W,
                      const float* __restrict__ bo, float* __restrict__ out) {
    int warp = (blockIdx.x * blockDim.x + threadIdx.x) >> 5;
    int lane = threadIdx.x & 31;
    if (warp >= N_) return;
    const float* row = h + (size_t)warp * 256;
    float a0 = 0.f, a1 = 0.f;
#pragma unroll
    for (int k = lane; k < 256; k += 32) {
        float v = row[k];
        a0 += v * W[k * 2 + 0];
        a1 += v * W[k * 2 + 1];
    }
#pragma unroll
    for (int d = 16; d > 0; d >>= 1) {
        a0 += __shfl_down_sync(0xffffffffu, a0, d);
        a1 += __shfl_down_sync(0xffffffffu, a1, d);
    }
    if (lane == 0) {
        out[(size_t)warp * 2 + 0] = a0 + bo[0];
        out[(size_t)warp * 2 + 1] = a1 + bo[1];
    }
}

// ---------------------------------------------------------------------------
// Launch
// ---------------------------------------------------------------------------
extern "C" void kernel_launch(void* const* d_in, const int* in_sizes, int n_in,
                              void* d_out, int out_size) {
    const float* x = (const float*)d_in[0];
    const int* ei = (const int*)d_in[1];
    const int* src = ei;
    const int* dst = ei + E_;
    const float* L[3][8];
    for (int l = 0; l < 3; l++)
        for (int p = 0; p < 8; p++)
            L[l][p] = (const float*)d_in[2 + l * 8 + p];
    const float* outW = (const float*)d_in[26];
    const float* outb = (const float*)d_in[27];
    float* out = (float*)d_out;

    // True device pointers for all cross-kernel scratch
    float *b0p = nullptr, *b1p = nullptr;
    __nv_bfloat16 *whp = nullptr, *wlp = nullptr;
    cudaGetSymbolAddress((void**)&b0p, g_buf0);
    cudaGetSymbolAddress((void**)&b1p, g_buf1);
    cudaGetSymbolAddress((void**)&whp, g_wt_hi);
    cudaGetSymbolAddress((void**)&wlp, g_wt_lo);

    cudaFuncSetAttribute(k_mma<0, true>, cudaFuncAttributeMaxDynamicSharedMemorySize, SMEM_BYTES);
    cudaFuncSetAttribute(k_mma<1, true>, cudaFuncAttributeMaxDynamicSharedMemorySize, SMEM_BYTES);
    cudaFuncSetAttribute(k_mma<1, false>, cudaFuncAttributeMaxDynamicSharedMemorySize, SMEM_BYTES);

    // CSR: count(0), scanzero(1), fill(2)
    k_count<<<512, 256>>>(dst);
    k_scanzero<<<1, 1024>>>();
    k_fill<<<512, 256>>>(src, dst);

    int aggBlocks = (N_ + 7) / 8;
    dim3 gg((N_ + 127) / 128, 2);  // 782 x 2

    // index 3 = k_agg<128> (ncu target)
    k_agg<128><<<aggBlocks, 256>>>(x, b0p);

    // weight split/transpose (once per launch)
    k_wprep<<<dim3(256, 1, 6), 256>>>(L[0][0], L[0][6], L[1][0], L[1][6],
                                      L[2][0], L[2][6], whp, wlp);

    // Layer 1 (K=128 for first GEMM)
    k_mma<0, true><<<gg, 256, SMEM_BYTES>>>(b0p, whp + 0, wlp + 0,
        L[0][1], L[0][2], L[0][3], L[0][4], L[0][5], b1p, N_, 128);
    k_mma<1, true><<<gg, 256, SMEM_BYTES>>>(b1p, whp + 32768, wlp + 32768,
        L[0][7], nullptr, nullptr, nullptr, nullptr, b0p, N_, 256);

    // Layer 2
    k_agg<256><<<aggBlocks, 256>>>(b0p, b1p);
    k_mma<0, true><<<gg, 256, SMEM_BYTES>>>(b1p, whp + 98304, wlp + 98304,
        L[1][1], L[1][2], L[1][3], L[1][4], L[1][5], b0p, N_, 256);
    k_mma<1, true><<<gg, 256, SMEM_BYTES>>>(b0p, whp + 163840, wlp + 163840,
        L[1][7], nullptr, nullptr, nullptr, nullptr, b1p, N_, 256);

    // Layer 3 (no final ReLU)
    k_agg<256><<<aggBlocks, 256>>>(b1p, b0p);
    k_mma<0, true><<<gg, 256, SMEM_BYTES>>>(b0p, whp + 229376, wlp + 229376,
        L[2][1], L[2][2], L[2][3], L[2][4], L[2][5], b1p, N_, 256);
    k_mma<1, false><<<gg, 256, SMEM_BYTES>>>(b1p, whp + 294912, wlp + 294912,
        L[2][7], nullptr, nullptr, nullptr, nullptr, b0p, N_, 256);

    // Output head
    k_out<<<(N_ + 7) / 8, 256>>>(b0p, outW, outb, out);
}